// round 2
// baseline (speedup 1.0000x reference)
#include <cuda_runtime.h>

// Problem constants
#define B_   8
#define T_   2048
#define N_   512
#define M_   (B_*T_)      // 16384
#define L_   128          // scan chunk length
#define NCH_ (T_/L_)      // 16 chunks

// Scratch (allocation-free rule: __device__ globals)
__device__ float g_xr[M_*N_];
__device__ float g_xi[M_*N_];
__device__ float g_endr[B_*NCH_*N_];
__device__ float g_endi[B_*NCH_*N_];

typedef unsigned long long ull;

__device__ __forceinline__ ull pk2(float x, float y){
    ull r; asm("mov.b64 %0, {%1, %2};" : "=l"(r) : "f"(x), "f"(y)); return r;
}
__device__ __forceinline__ ull fma2(ull a, ull b, ull c){
    ull d; asm("fma.rn.f32x2 %0, %1, %2, %3;" : "=l"(d) : "l"(a), "l"(b), "l"(c)); return d;
}
__device__ __forceinline__ float2 upk(ull p){
    float2 v; asm("mov.b64 {%0, %1}, %2;" : "=f"(v.x), "=f"(v.y) : "l"(p)); return v;
}

// ---------------------------------------------------------------------------
// GEMM 1: out[m,n] = sum_k (gamma[k]*u[m,k]) * W[k,n]
// BM=128, BN=128, BK=16, 256 threads, 8x8 per thread via f32x2.
// which==0 -> g_xr, which==1 -> g_xi
// ---------------------------------------------------------------------------
__global__ __launch_bounds__(256) void gemm_uB(const float* __restrict__ A,
                                               const float* __restrict__ W,
                                               const float* __restrict__ gamma,
                                               int which)
{
    __shared__ float As[16][128];
    __shared__ float Ws[16][128];
    float* out = which ? g_xi : g_xr;

    const int tid = threadIdx.x;
    const int m0  = blockIdx.x * 128;
    const int n0  = blockIdx.y * 128;

    // A-load mapping: 2 rows x 4 floats each
    const int lrow = tid >> 2;           // 0..63
    const int lkg  = (tid & 3) * 4;      // 0,4,8,12
    // W-load mapping: 1 row x 8 floats (2 float4)
    const int wk = tid >> 4;             // 0..15
    const int wn = (tid & 15) * 8;
    // compute mapping
    const int rowBase = (tid >> 4) * 8;
    const int colBase = (tid & 15) * 8;

    ull acc[8][4];
    #pragma unroll
    for (int i = 0; i < 8; i++)
        #pragma unroll
        for (int j = 0; j < 4; j++) acc[i][j] = 0ULL;

    for (int kt = 0; kt < N_; kt += 16) {
        float4 a0 = *(const float4*)&A[(size_t)(m0 + lrow)      * N_ + kt + lkg];
        float4 a1 = *(const float4*)&A[(size_t)(m0 + lrow + 64) * N_ + kt + lkg];
        float4 gg = *(const float4*)&gamma[kt + lkg];
        float4 w0 = *(const float4*)&W[(size_t)(kt + wk) * N_ + n0 + wn];
        float4 w1 = *(const float4*)&W[(size_t)(kt + wk) * N_ + n0 + wn + 4];

        As[lkg+0][lrow]      = a0.x * gg.x;
        As[lkg+1][lrow]      = a0.y * gg.y;
        As[lkg+2][lrow]      = a0.z * gg.z;
        As[lkg+3][lrow]      = a0.w * gg.w;
        As[lkg+0][lrow + 64] = a1.x * gg.x;
        As[lkg+1][lrow + 64] = a1.y * gg.y;
        As[lkg+2][lrow + 64] = a1.z * gg.z;
        As[lkg+3][lrow + 64] = a1.w * gg.w;
        *(float4*)&Ws[wk][wn]     = w0;
        *(float4*)&Ws[wk][wn + 4] = w1;
        __syncthreads();

        #pragma unroll
        for (int k = 0; k < 16; k++) {
            float4 av0 = *(const float4*)&As[k][rowBase];
            float4 av1 = *(const float4*)&As[k][rowBase + 4];
            float4 bv0 = *(const float4*)&Ws[k][colBase];
            float4 bv1 = *(const float4*)&Ws[k][colBase + 4];
            ull bp[4] = { pk2(bv0.x, bv0.y), pk2(bv0.z, bv0.w),
                          pk2(bv1.x, bv1.y), pk2(bv1.z, bv1.w) };
            float av[8] = { av0.x, av0.y, av0.z, av0.w, av1.x, av1.y, av1.z, av1.w };
            #pragma unroll
            for (int i = 0; i < 8; i++) {
                ull ad = pk2(av[i], av[i]);
                #pragma unroll
                for (int j = 0; j < 4; j++) acc[i][j] = fma2(ad, bp[j], acc[i][j]);
            }
        }
        __syncthreads();
    }

    #pragma unroll
    for (int i = 0; i < 8; i++) {
        const size_t m = m0 + rowBase + i;
        #pragma unroll
        for (int j = 0; j < 4; j++)
            *(ull*)&out[m * N_ + n0 + colBase + 2*j] = acc[i][j];
    }
}

// ---------------------------------------------------------------------------
// Scan pass 1: chunk-local recurrence x_t = lam*x_{t-1} + u_t (in place),
// record chunk-final state.
// ---------------------------------------------------------------------------
__global__ __launch_bounds__(256) void scan_local(const float* __restrict__ nu,
                                                  const float* __restrict__ theta)
{
    int gid = blockIdx.x * blockDim.x + threadIdx.x;   // 0 .. B*NCH*N-1
    int n = gid % N_;
    int c = (gid / N_) % NCH_;
    int b = gid / (N_ * NCH_);

    float en  = expf(nu[n]);
    float mag = expf(-en);
    float th  = theta[n];
    float lr  = mag * cosf(th);
    float li  = mag * sinf(th);

    size_t base = ((size_t)(b * T_ + c * L_)) * N_ + n;
    float xr = 0.f, xi = 0.f;
    #pragma unroll 4
    for (int t = 0; t < L_; t++) {
        size_t idx = base + (size_t)t * N_;
        float ur = g_xr[idx];
        float ui = g_xi[idx];
        float nr = fmaf(lr, xr, fmaf(-li, xi, ur));
        float ni = fmaf(lr, xi, fmaf( li, xr, ui));
        xr = nr; xi = ni;
        g_xr[idx] = xr;
        g_xi[idx] = xi;
    }
    g_endr[(b * NCH_ + c) * N_ + n] = xr;
    g_endi[(b * NCH_ + c) * N_ + n] = xi;
}

// ---------------------------------------------------------------------------
// Scan pass 2: fold in carry from previous chunks:
// x[c*L + s] += lam^{s+1} * carry, carry = sum_{j<c} end[j]*lamL^{c-1-j}
// ---------------------------------------------------------------------------
__global__ __launch_bounds__(256) void scan_fix(const float* __restrict__ nu,
                                                const float* __restrict__ theta)
{
    int gid = blockIdx.x * blockDim.x + threadIdx.x;
    int n = gid % N_;
    int c = (gid / N_) % NCH_;
    int b = gid / (N_ * NCH_);
    if (c == 0) return;

    float en  = expf(nu[n]);
    float mag = expf(-en);
    float th  = theta[n];
    float lr  = mag * cosf(th);
    float li  = mag * sinf(th);

    // lam^L computed exactly: |lam|^L = exp(-L*exp(nu)), angle = L*theta
    float magL = expf(-(float)L_ * en);
    float aL   = (float)L_ * th;
    float lLr  = magL * cosf(aL);
    float lLi  = magL * sinf(aL);

    // Horner: carry = sum_{j=0..c-1} end[j] * lamL^{c-1-j}
    float cr = 0.f, ci = 0.f;
    for (int j = 0; j < c; j++) {
        float er = g_endr[(b * NCH_ + j) * N_ + n];
        float ei = g_endi[(b * NCH_ + j) * N_ + n];
        float tr = cr * lLr - ci * lLi + er;
        float ti = cr * lLi + ci * lLr + ei;
        cr = tr; ci = ti;
    }

    size_t base = ((size_t)(b * T_ + c * L_)) * N_ + n;
    float pr = lr, pi = li;   // lam^{s+1}, s=0
    #pragma unroll 4
    for (int t = 0; t < L_; t++) {
        size_t idx = base + (size_t)t * N_;
        g_xr[idx] += pr * cr - pi * ci;
        g_xi[idx] += pr * ci + pi * cr;
        float npr = pr * lr - pi * li;
        float npi = pr * li + pi * lr;
        pr = npr; pi = npi;
    }
}

// ---------------------------------------------------------------------------
// GEMM 2: y[m,n] = sum_k ( xr[m,k]*Cre[k,n] - xi[m,k]*Cim[k,n] ) + D[n]*u[m,n]
// ---------------------------------------------------------------------------
__global__ __launch_bounds__(256) void gemm_xC(const float* __restrict__ Cre,
                                               const float* __restrict__ Cim,
                                               const float* __restrict__ D,
                                               const float* __restrict__ u,
                                               float* __restrict__ y)
{
    __shared__ float Ar[16][128];
    __shared__ float Ai[16][128];
    __shared__ float Wr[16][128];
    __shared__ float Wi[16][128];   // stored negated

    const int tid = threadIdx.x;
    const int m0  = blockIdx.x * 128;
    const int n0  = blockIdx.y * 128;

    const int lrow = tid >> 2;
    const int lkg  = (tid & 3) * 4;
    const int wk = tid >> 4;
    const int wn = (tid & 15) * 8;
    const int rowBase = (tid >> 4) * 8;
    const int colBase = (tid & 15) * 8;

    ull acc[8][4];
    #pragma unroll
    for (int i = 0; i < 8; i++)
        #pragma unroll
        for (int j = 0; j < 4; j++) acc[i][j] = 0ULL;

    for (int kt = 0; kt < N_; kt += 16) {
        float4 ar0 = *(const float4*)&g_xr[(size_t)(m0 + lrow)      * N_ + kt + lkg];
        float4 ar1 = *(const float4*)&g_xr[(size_t)(m0 + lrow + 64) * N_ + kt + lkg];
        float4 ai0 = *(const float4*)&g_xi[(size_t)(m0 + lrow)      * N_ + kt + lkg];
        float4 ai1 = *(const float4*)&g_xi[(size_t)(m0 + lrow + 64) * N_ + kt + lkg];
        float4 w0 = *(const float4*)&Cre[(size_t)(kt + wk) * N_ + n0 + wn];
        float4 w1 = *(const float4*)&Cre[(size_t)(kt + wk) * N_ + n0 + wn + 4];
        float4 v0 = *(const float4*)&Cim[(size_t)(kt + wk) * N_ + n0 + wn];
        float4 v1 = *(const float4*)&Cim[(size_t)(kt + wk) * N_ + n0 + wn + 4];

        Ar[lkg+0][lrow]      = ar0.x; Ar[lkg+1][lrow]      = ar0.y;
        Ar[lkg+2][lrow]      = ar0.z; Ar[lkg+3][lrow]      = ar0.w;
        Ar[lkg+0][lrow + 64] = ar1.x; Ar[lkg+1][lrow + 64] = ar1.y;
        Ar[lkg+2][lrow + 64] = ar1.z; Ar[lkg+3][lrow + 64] = ar1.w;
        Ai[lkg+0][lrow]      = ai0.x; Ai[lkg+1][lrow]      = ai0.y;
        Ai[lkg+2][lrow]      = ai0.z; Ai[lkg+3][lrow]      = ai0.w;
        Ai[lkg+0][lrow + 64] = ai1.x; Ai[lkg+1][lrow + 64] = ai1.y;
        Ai[lkg+2][lrow + 64] = ai1.z; Ai[lkg+3][lrow + 64] = ai1.w;
        *(float4*)&Wr[wk][wn]     = w0;
        *(float4*)&Wr[wk][wn + 4] = w1;
        Wi[wk][wn+0] = -v0.x; Wi[wk][wn+1] = -v0.y;
        Wi[wk][wn+2] = -v0.z; Wi[wk][wn+3] = -v0.w;
        Wi[wk][wn+4] = -v1.x; Wi[wk][wn+5] = -v1.y;
        Wi[wk][wn+6] = -v1.z; Wi[wk][wn+7] = -v1.w;
        __syncthreads();

        #pragma unroll
        for (int k = 0; k < 16; k++) {
            float4 arv0 = *(const float4*)&Ar[k][rowBase];
            float4 arv1 = *(const float4*)&Ar[k][rowBase + 4];
            float4 aiv0 = *(const float4*)&Ai[k][rowBase];
            float4 aiv1 = *(const float4*)&Ai[k][rowBase + 4];
            float4 brv0 = *(const float4*)&Wr[k][colBase];
            float4 brv1 = *(const float4*)&Wr[k][colBase + 4];
            float4 biv0 = *(const float4*)&Wi[k][colBase];
            float4 biv1 = *(const float4*)&Wi[k][colBase + 4];
            ull br[4] = { pk2(brv0.x, brv0.y), pk2(brv0.z, brv0.w),
                          pk2(brv1.x, brv1.y), pk2(brv1.z, brv1.w) };
            ull bi[4] = { pk2(biv0.x, biv0.y), pk2(biv0.z, biv0.w),
                          pk2(biv1.x, biv1.y), pk2(biv1.z, biv1.w) };
            float arr[8] = { arv0.x, arv0.y, arv0.z, arv0.w, arv1.x, arv1.y, arv1.z, arv1.w };
            float aii[8] = { aiv0.x, aiv0.y, aiv0.z, aiv0.w, aiv1.x, aiv1.y, aiv1.z, aiv1.w };
            #pragma unroll
            for (int i = 0; i < 8; i++) {
                ull adr = pk2(arr[i], arr[i]);
                ull adi = pk2(aii[i], aii[i]);
                #pragma unroll
                for (int j = 0; j < 4; j++) {
                    acc[i][j] = fma2(adr, br[j], acc[i][j]);
                    acc[i][j] = fma2(adi, bi[j], acc[i][j]);
                }
            }
        }
        __syncthreads();
    }

    #pragma unroll
    for (int i = 0; i < 8; i++) {
        const size_t m = m0 + rowBase + i;
        #pragma unroll
        for (int j = 0; j < 4; j++) {
            const int n = n0 + colBase + 2*j;
            float2 v  = upk(acc[i][j]);
            float2 dd = *(const float2*)&D[n];
            float2 uu = *(const float2*)&u[m * N_ + n];
            v.x = fmaf(dd.x, uu.x, v.x);
            v.y = fmaf(dd.y, uu.y, v.y);
            *(float2*)&y[m * N_ + n] = v;
        }
    }
}

// ---------------------------------------------------------------------------
extern "C" void kernel_launch(void* const* d_in, const int* in_sizes, int n_in,
                              void* d_out, int out_size)
{
    const float* u     = (const float*)d_in[0];
    const float* C_re  = (const float*)d_in[1];
    const float* C_im  = (const float*)d_in[2];
    const float* B_re  = (const float*)d_in[3];
    const float* B_im  = (const float*)d_in[4];
    const float* D     = (const float*)d_in[5];
    const float* nu    = (const float*)d_in[6];
    const float* theta = (const float*)d_in[7];
    const float* gamma = (const float*)d_in[8];
    float* y = (float*)d_out;

    dim3 blk(256);
    dim3 grd(M_ / 128, N_ / 128);

    gemm_uB<<<grd, blk>>>(u, B_re, gamma, 0);
    gemm_uB<<<grd, blk>>>(u, B_im, gamma, 1);

    int scan_threads = B_ * NCH_ * N_;          // 65536
    scan_local<<<scan_threads / 256, 256>>>(nu, theta);
    scan_fix<<<scan_threads / 256, 256>>>(nu, theta);

    gemm_xC<<<grd, blk>>>(C_re, C_im, D, u, y);
}

// round 4
// speedup vs baseline: 2.9116x; 2.9116x over previous
#include <cuda_runtime.h>
#include <cstdint>

#define B_   8
#define T_   2048
#define N_   512
#define M_   (B_*T_)      // 16384
#define L_   64           // scan chunk length
#define NCH_ (T_/L_)      // 32

typedef unsigned long long ull;

// Scratch
__device__ float2 g_x[M_*N_];                 // interleaved complex (re, im)
__device__ float2 g_end[B_*NCH_*N_];
// Pre-transposed/split/swizzled weight tiles: [plane hi/lo][nblk][kblk][tile 1024 uint4]
__device__ uint4 g_W1[2][8][8][1024];         // GEMM1 B'' (Neff=1024, K=512)
__device__ uint4 g_W2[2][4][16][1024];        // GEMM2 B'  (N=512, Keff=1024)

// ---------------------------------------------------------------------------
// Helpers
// ---------------------------------------------------------------------------
__device__ __forceinline__ uint32_t s2u(const void* p){
    uint32_t a;
    asm("{ .reg .u64 t; cvta.to.shared.u64 t, %1; cvt.u32.u64 %0, t; }" : "=r"(a) : "l"(p));
    return a;
}
#define SWZ(o) ((uint32_t)(o) ^ ((((uint32_t)(o))>>3)&0x70u))

// Split (x0,x1) into hi/lo bf16x2 (elem0 in low half)
__device__ __forceinline__ void split2(float x0, float x1, uint32_t &h, uint32_t &l){
    uint32_t hh;
    asm("cvt.rn.bf16x2.f32 %0, %1, %2;" : "=r"(hh) : "f"(x1), "f"(x0));
    float h0 = __uint_as_float(hh << 16);
    float h1 = __uint_as_float(hh & 0xFFFF0000u);
    uint32_t ll;
    float r0 = x0 - h0, r1 = x1 - h1;
    asm("cvt.rn.bf16x2.f32 %0, %1, %2;" : "=r"(ll) : "f"(r1), "f"(r0));
    h = hh; l = ll;
}

__device__ __forceinline__ uint4 ldsm4(uint32_t addr){
    uint4 r;
    asm volatile("ldmatrix.sync.aligned.m8n8.x4.shared.b16 {%0,%1,%2,%3}, [%4];"
        : "=r"(r.x), "=r"(r.y), "=r"(r.z), "=r"(r.w) : "r"(addr));
    return r;
}
__device__ __forceinline__ void mma16816(float* c, uint4 a, uint32_t b0, uint32_t b1){
    asm volatile("mma.sync.aligned.m16n8k16.row.col.f32.bf16.bf16.f32 "
        "{%0,%1,%2,%3}, {%4,%5,%6,%7}, {%8,%9}, {%0,%1,%2,%3};"
        : "+f"(c[0]), "+f"(c[1]), "+f"(c[2]), "+f"(c[3])
        : "r"(a.x), "r"(a.y), "r"(a.z), "r"(a.w), "r"(b0), "r"(b1));
}
__device__ __forceinline__ void cpasync16(uint32_t dst, const void* src){
    asm volatile("cp.async.cg.shared.global [%0], [%1], 16;" :: "r"(dst), "l"(src));
}

// ---------------------------------------------------------------------------
// Prepass: transpose + hi/lo split + swizzle weights into tiled layout.
//   W1: row j = neff (0..1023): src (j&1 ? B_im : B_re)[k][j>>1] * gamma[k]
//   W2: row j = n (0..511), col keff: keff even -> C_re[keff/2][j], odd -> -C_im
// ---------------------------------------------------------------------------
__global__ __launch_bounds__(256) void prep_W(const float* __restrict__ Bre,
                                              const float* __restrict__ Bim,
                                              const float* __restrict__ Cre,
                                              const float* __restrict__ Cim,
                                              const float* __restrict__ gamma)
{
    int v = blockIdx.x * 256 + threadIdx.x;        // 0 .. 131071
    if (v < 65536){
        int j = v >> 6, c = v & 63;                // j: neff row, c: 8-k chunk
        int nb = j >> 7, jl = j & 127, kb = c >> 3, cl = c & 7;
        const float* src = (j & 1) ? Bim : Bre;
        int n = j >> 1;
        float vs[8];
        #pragma unroll
        for (int kk = 0; kk < 8; kk++){
            int k = c*8 + kk;
            vs[kk] = src[(size_t)k*N_ + n] * gamma[k];
        }
        uint4 H, L;
        split2(vs[0], vs[1], H.x, L.x);
        split2(vs[2], vs[3], H.y, L.y);
        split2(vs[4], vs[5], H.z, L.z);
        split2(vs[6], vs[7], H.w, L.w);
        int unit = jl*8 + (cl ^ (jl & 7));
        g_W1[0][nb][kb][unit] = H;
        g_W1[1][nb][kb][unit] = L;
    } else {
        v -= 65536;
        int j = v >> 7, c = v & 127;               // j: n row, c: 8-keff chunk
        int nb = j >> 7, jl = j & 127, kb = c >> 3, cl = c & 7;
        float vs[8];
        #pragma unroll
        for (int e = 0; e < 8; e++){
            int keff = c*8 + e;
            int k = keff >> 1;
            float w = (keff & 1) ? -Cim[(size_t)k*N_ + j] : Cre[(size_t)k*N_ + j];
            vs[e] = w;
        }
        uint4 H, L;
        split2(vs[0], vs[1], H.x, L.x);
        split2(vs[2], vs[3], H.y, L.y);
        split2(vs[4], vs[5], H.z, L.z);
        split2(vs[6], vs[7], H.w, L.w);
        int unit = jl*8 + (cl ^ (jl & 7));
        g_W2[0][nb][kb][unit] = H;
        g_W2[1][nb][kb][unit] = L;
    }
}

// ---------------------------------------------------------------------------
// HMMA GEMM. MODE 1: g_x = (u) @ W1 (gamma pre-folded), M=16384, Neff=1024, K=512
//            MODE 2: y = flat(g_x) @ W2 + D*u,          M=16384, N=512, Keff=1024
// CTA tile 128x128x64, 8 warps (4x2), warp tile 32x64. bf16 hi/lo 3-product split.
// ---------------------------------------------------------------------------
template<int MODE>
__global__ __launch_bounds__(256, 2) void gemm_tc(const float* __restrict__ Aglob,
                                                  const float* __restrict__ Dv,
                                                  const float* __restrict__ uu,
                                                  float* __restrict__ yout)
{
    constexpr int LDA = (MODE == 1) ? 512 : 1024;
    constexpr int KIT = (MODE == 1) ? 8 : 16;

    extern __shared__ char sm[];
    const uint32_t sb = s2u(sm);
    const uint32_t AH = 0, AL = 16384, BH = 32768, BL = 49152;

    const int tid  = threadIdx.x;
    const int lane = tid & 31, warp = tid >> 5;
    const int wm = warp >> 1, wn = warp & 1;
    const int m0 = blockIdx.x * 128;
    const int nb = blockIdx.y;

    const float* Abase = (MODE == 1) ? Aglob : (const float*)g_x;

    float acc[2][8][4] = {};

    const int arow = tid >> 1;
    const int akg  = (tid & 1) * 32;
    const float* aptr = Abase + (size_t)(m0 + arow) * LDA + akg;

    for (int kb = 0; kb < KIT; kb++){
        // B tiles: straight pre-swizzled copies via cp.async
        const uint4* wh = (MODE == 1) ? &g_W1[0][nb][kb][0] : &g_W2[0][nb][kb][0];
        const uint4* wl = (MODE == 1) ? &g_W1[1][nb][kb][0] : &g_W2[1][nb][kb][0];
        #pragma unroll
        for (int i = 0; i < 4; i++){
            cpasync16(sb + BH + (tid + 256*i)*16, wh + tid + 256*i);
            cpasync16(sb + BL + (tid + 256*i)*16, wl + tid + 256*i);
        }
        asm volatile("cp.async.commit_group;");

        // A tile: coalesced fp32 load -> hi/lo bf16 split -> swizzled smem
        {
            const float4* ap = (const float4*)(aptr + kb*64);
            float4 f[8];
            #pragma unroll
            for (int j = 0; j < 8; j++) f[j] = ap[j];
            #pragma unroll
            for (int j = 0; j < 4; j++){
                uint4 H, L;
                split2(f[2*j].x,   f[2*j].y,   H.x, L.x);
                split2(f[2*j].z,   f[2*j].w,   H.y, L.y);
                split2(f[2*j+1].x, f[2*j+1].y, H.z, L.z);
                split2(f[2*j+1].z, f[2*j+1].w, H.w, L.w);
                uint32_t off = SWZ(arow*128 + ((tid&1)*4 + j)*16);
                *(uint4*)(sm + AH + off) = H;
                *(uint4*)(sm + AL + off) = L;
            }
        }
        asm volatile("cp.async.wait_group 0;" ::: "memory");
        __syncthreads();

        #pragma unroll
        for (int kk = 0; kk < 4; kk++){
            uint4 ah[2], al[2];
            #pragma unroll
            for (int mt = 0; mt < 2; mt++){
                uint32_t off = SWZ((wm*32 + mt*16 + (lane&15))*128 + (kk*2 + (lane>>4))*16);
                ah[mt] = ldsm4(sb + AH + off);
                al[mt] = ldsm4(sb + AL + off);
            }
            #pragma unroll
            for (int bt = 0; bt < 4; bt++){
                uint32_t off = SWZ((wn*64 + bt*16 + (lane&7) + ((lane>>4)<<3))*128
                                   + (kk*2 + ((lane>>3)&1))*16);
                uint4 bh = ldsm4(sb + BH + off);
                uint4 bl = ldsm4(sb + BL + off);
                #pragma unroll
                for (int mt = 0; mt < 2; mt++){
                    mma16816(acc[mt][2*bt],   ah[mt], bh.x, bh.y);
                    mma16816(acc[mt][2*bt],   al[mt], bh.x, bh.y);
                    mma16816(acc[mt][2*bt],   ah[mt], bl.x, bl.y);
                    mma16816(acc[mt][2*bt+1], ah[mt], bh.z, bh.w);
                    mma16816(acc[mt][2*bt+1], al[mt], bh.z, bh.w);
                    mma16816(acc[mt][2*bt+1], ah[mt], bl.z, bl.w);
                }
            }
        }
        __syncthreads();
    }

    // Epilogue
    const int mrow = lane >> 2;
    const int ncol = (lane & 3) * 2;
    if (MODE == 1){
        #pragma unroll
        for (int mt = 0; mt < 2; mt++){
            #pragma unroll
            for (int nf = 0; nf < 8; nf++){
                int m    = m0 + wm*32 + mt*16 + mrow;
                int neff = nb*128 + wn*64 + nf*8 + ncol;
                int nc   = neff >> 1;
                g_x[(size_t)m*N_ + nc]     = make_float2(acc[mt][nf][0], acc[mt][nf][1]);
                g_x[(size_t)(m+8)*N_ + nc] = make_float2(acc[mt][nf][2], acc[mt][nf][3]);
            }
        }
    } else {
        #pragma unroll
        for (int mt = 0; mt < 2; mt++){
            #pragma unroll
            for (int nf = 0; nf < 8; nf++){
                int m = m0 + wm*32 + mt*16 + mrow;
                int n = nb*128 + wn*64 + nf*8 + ncol;
                float2 d = *(const float2*)&Dv[n];
                size_t i0 = (size_t)m*N_ + n;
                size_t i1 = (size_t)(m+8)*N_ + n;
                float2 u0 = *(const float2*)&uu[i0];
                float2 u1 = *(const float2*)&uu[i1];
                float2 y0 = make_float2(fmaf(d.x, u0.x, acc[mt][nf][0]),
                                        fmaf(d.y, u0.y, acc[mt][nf][1]));
                float2 y1 = make_float2(fmaf(d.x, u1.x, acc[mt][nf][2]),
                                        fmaf(d.y, u1.y, acc[mt][nf][3]));
                *(float2*)&yout[i0] = y0;
                *(float2*)&yout[i1] = y1;
            }
        }
    }
}

// ---------------------------------------------------------------------------
// Scan pass 1: chunk-local recurrence x_t = lam*x_{t-1} + u_t (in place)
// ---------------------------------------------------------------------------
__global__ __launch_bounds__(256) void scan_local(const float* __restrict__ nu,
                                                  const float* __restrict__ theta)
{
    int gid = blockIdx.x * 256 + threadIdx.x;   // 131072 threads
    int n = gid & (N_-1);
    int c = (gid >> 9) & (NCH_-1);
    int b = gid >> 14;

    float en  = expf(nu[n]);
    float mag = expf(-en);
    float th  = theta[n];
    float lr  = mag * cosf(th);
    float li  = mag * sinf(th);

    float2* p = g_x + ((size_t)(b*T_ + c*L_))*N_ + n;
    float xr = 0.f, xi = 0.f;
    for (int t0 = 0; t0 < L_; t0 += 8){
        float2 v[8];
        #pragma unroll
        for (int j = 0; j < 8; j++) v[j] = p[(size_t)(t0+j)*N_];
        #pragma unroll
        for (int j = 0; j < 8; j++){
            float nr = fmaf(lr, xr, fmaf(-li, xi, v[j].x));
            float ni = fmaf(lr, xi, fmaf( li, xr, v[j].y));
            xr = nr; xi = ni;
            p[(size_t)(t0+j)*N_] = make_float2(xr, xi);
        }
    }
    g_end[(b*NCH_ + c)*N_ + n] = make_float2(xr, xi);
}

// ---------------------------------------------------------------------------
// Scan pass 2: fold carry from previous chunks
// ---------------------------------------------------------------------------
__global__ __launch_bounds__(256) void scan_fix(const float* __restrict__ nu,
                                                const float* __restrict__ theta)
{
    int gid = blockIdx.x * 256 + threadIdx.x;
    int n = gid & (N_-1);
    int c = (gid >> 9) & (NCH_-1);
    int b = gid >> 14;
    if (c == 0) return;

    float en  = expf(nu[n]);
    float mag = expf(-en);
    float th  = theta[n];
    float lr  = mag * cosf(th);
    float li  = mag * sinf(th);

    float magL = expf(-(float)L_ * en);
    float aL   = (float)L_ * th;
    float lLr  = magL * cosf(aL);
    float lLi  = magL * sinf(aL);

    float cr = 0.f, ci = 0.f;
    for (int j = 0; j < c; j++){
        float2 e = g_end[(b*NCH_ + j)*N_ + n];
        float tr = cr*lLr - ci*lLi + e.x;
        float ti = cr*lLi + ci*lLr + e.y;
        cr = tr; ci = ti;
    }

    float2* p = g_x + ((size_t)(b*T_ + c*L_))*N_ + n;
    float pr = lr, pi = li;
    for (int t0 = 0; t0 < L_; t0 += 8){
        float2 v[8];
        #pragma unroll
        for (int j = 0; j < 8; j++) v[j] = p[(size_t)(t0+j)*N_];
        #pragma unroll
        for (int j = 0; j < 8; j++){
            v[j].x += pr*cr - pi*ci;
            v[j].y += pr*ci + pi*cr;
            p[(size_t)(t0+j)*N_] = v[j];
            float npr = pr*lr - pi*li;
            float npi = pr*li + pi*lr;
            pr = npr; pi = npi;
        }
    }
}

// ---------------------------------------------------------------------------
extern "C" void kernel_launch(void* const* d_in, const int* in_sizes, int n_in,
                              void* d_out, int out_size)
{
    const float* u     = (const float*)d_in[0];
    const float* C_re  = (const float*)d_in[1];
    const float* C_im  = (const float*)d_in[2];
    const float* B_re  = (const float*)d_in[3];
    const float* B_im  = (const float*)d_in[4];
    const float* D     = (const float*)d_in[5];
    const float* nu    = (const float*)d_in[6];
    const float* theta = (const float*)d_in[7];
    const float* gamma = (const float*)d_in[8];
    float* y = (float*)d_out;

    const int SMEM = 65536;
    cudaFuncSetAttribute(gemm_tc<1>, cudaFuncAttributeMaxDynamicSharedMemorySize, SMEM);
    cudaFuncSetAttribute(gemm_tc<2>, cudaFuncAttributeMaxDynamicSharedMemorySize, SMEM);

    prep_W<<<512, 256>>>(B_re, B_im, C_re, C_im, gamma);

    gemm_tc<1><<<dim3(M_/128, 8), 256, SMEM>>>(u, D, u, (float*)0);

    int scan_threads = B_ * NCH_ * N_;          // 131072
    scan_local<<<scan_threads/256, 256>>>(nu, theta);
    scan_fix<<<scan_threads/256, 256>>>(nu, theta);

    gemm_tc<2><<<dim3(M_/128, 4), 256, SMEM>>>((const float*)0, D, u, y);
}

// round 6
// speedup vs baseline: 3.3462x; 1.1493x over previous
#include <cuda_runtime.h>
#include <cuda_fp16.h>
#include <cstdint>

#define B_   8
#define T_   2048
#define N_   512
#define M_   (B_*T_)      // 16384
#define L_   64           // scan chunk length
#define NCH_ (T_/L_)      // 32

#define WSCALE 64.0f
#define WINV   (1.0f/64.0f)

typedef unsigned long long ull;

// Scratch
__device__ float2 g_x[M_*N_];                 // interleaved complex (re, im)
__device__ float2 g_end[B_*NCH_*N_];
// Pre-transposed/split/swizzled fp16 weight tiles (scaled by WSCALE):
// [plane hi/lo][nblk][kblk][tile 1024 uint4]
__device__ uint4 g_W1[2][8][8][1024];         // GEMM1 B'' (Neff=1024, K=512)
__device__ uint4 g_W2[2][4][16][1024];        // GEMM2 B'  (N=512, Keff=1024)

// ---------------------------------------------------------------------------
// Helpers
// ---------------------------------------------------------------------------
__device__ __forceinline__ uint32_t s2u(const void* p){
    uint32_t a;
    asm("{ .reg .u64 t; cvta.to.shared.u64 t, %1; cvt.u32.u64 %0, t; }" : "=r"(a) : "l"(p));
    return a;
}
#define SWZ(o) ((uint32_t)(o) ^ ((((uint32_t)(o))>>3)&0x70u))

// fp16 pack of two floats (elem0 in low half)
__device__ __forceinline__ uint32_t cvt2h(float x0, float x1){
    uint32_t r;
    asm("cvt.rn.f16x2.f32 %0, %1, %2;" : "=r"(r) : "f"(x1), "f"(x0));
    return r;
}
// fp16 hi/lo split of two floats
__device__ __forceinline__ void split2h(float x0, float x1, uint32_t &h, uint32_t &l){
    uint32_t hh = cvt2h(x0, x1);
    __half2 hv = *reinterpret_cast<__half2*>(&hh);
    float h0 = __low2float(hv), h1 = __high2float(hv);
    l = cvt2h(x0 - h0, x1 - h1);
    h = hh;
}

__device__ __forceinline__ uint4 ldsm4(uint32_t addr){
    uint4 r;
    asm volatile("ldmatrix.sync.aligned.m8n8.x4.shared.b16 {%0,%1,%2,%3}, [%4];"
        : "=r"(r.x), "=r"(r.y), "=r"(r.z), "=r"(r.w) : "r"(addr));
    return r;
}
__device__ __forceinline__ void mma16816(float* c, uint4 a, uint32_t b0, uint32_t b1){
    asm volatile("mma.sync.aligned.m16n8k16.row.col.f32.f16.f16.f32 "
        "{%0,%1,%2,%3}, {%4,%5,%6,%7}, {%8,%9}, {%0,%1,%2,%3};"
        : "+f"(c[0]), "+f"(c[1]), "+f"(c[2]), "+f"(c[3])
        : "r"(a.x), "r"(a.y), "r"(a.z), "r"(a.w), "r"(b0), "r"(b1));
}
__device__ __forceinline__ void cpasync16(uint32_t dst, const void* src){
    asm volatile("cp.async.cg.shared.global [%0], [%1], 16;" :: "r"(dst), "l"(src));
}

// ---------------------------------------------------------------------------
// Prepass: transpose + fp16 hi/lo split (x WSCALE) + swizzle weights.
//   W1: row j = neff (0..1023): (j&1 ? B_im : B_re)[k][j>>1] * gamma[k]
//   W2: row j = n (0..511), col keff: even -> C_re[keff/2][j], odd -> -C_im
// ---------------------------------------------------------------------------
__global__ __launch_bounds__(256) void prep_W(const float* __restrict__ Bre,
                                              const float* __restrict__ Bim,
                                              const float* __restrict__ Cre,
                                              const float* __restrict__ Cim,
                                              const float* __restrict__ gamma)
{
    int v = blockIdx.x * 256 + threadIdx.x;        // 0 .. 131071
    if (v < 65536){
        int j = v >> 6, c = v & 63;
        int nb = j >> 7, jl = j & 127, kb = c >> 3, cl = c & 7;
        const float* src = (j & 1) ? Bim : Bre;
        int n = j >> 1;
        float vs[8];
        #pragma unroll
        for (int kk = 0; kk < 8; kk++){
            int k = c*8 + kk;
            vs[kk] = src[(size_t)k*N_ + n] * gamma[k] * WSCALE;
        }
        uint4 H, L;
        split2h(vs[0], vs[1], H.x, L.x);
        split2h(vs[2], vs[3], H.y, L.y);
        split2h(vs[4], vs[5], H.z, L.z);
        split2h(vs[6], vs[7], H.w, L.w);
        int unit = jl*8 + (cl ^ (jl & 7));
        g_W1[0][nb][kb][unit] = H;
        g_W1[1][nb][kb][unit] = L;
    } else {
        v -= 65536;
        int j = v >> 7, c = v & 127;
        int nb = j >> 7, jl = j & 127, kb = c >> 3, cl = c & 7;
        float vs[8];
        #pragma unroll
        for (int e = 0; e < 8; e++){
            int keff = c*8 + e;
            int k = keff >> 1;
            float w = (keff & 1) ? -Cim[(size_t)k*N_ + j] : Cre[(size_t)k*N_ + j];
            vs[e] = w * WSCALE;
        }
        uint4 H, L;
        split2h(vs[0], vs[1], H.x, L.x);
        split2h(vs[2], vs[3], H.y, L.y);
        split2h(vs[4], vs[5], H.z, L.z);
        split2h(vs[6], vs[7], H.w, L.w);
        int unit = jl*8 + (cl ^ (jl & 7));
        g_W2[0][nb][kb][unit] = H;
        g_W2[1][nb][kb][unit] = L;
    }
}

// ---------------------------------------------------------------------------
// HMMA GEMM, fp16 2-product (A single fp16, B split hi/lo), double-buffered.
// MODE 1: g_x = u @ W1,           M=16384, Neff=1024, K=512
// MODE 2: y = flat(g_x) @ W2 + D*u, M=16384, N=512, Keff=1024
// CTA tile 128x128x64, 8 warps (4x2), warp tile 32x64.
// ---------------------------------------------------------------------------
template<int MODE>
__global__ __launch_bounds__(256, 2) void gemm_tc(const float* __restrict__ Aglob,
                                                  const float* __restrict__ Dv,
                                                  const float* __restrict__ uu,
                                                  float* __restrict__ yout)
{
    constexpr int LDA = (MODE == 1) ? 512 : 1024;
    constexpr int KIT = (MODE == 1) ? 8 : 16;
    constexpr uint32_t STG = 49152;     // stage stride
    constexpr uint32_t AH = 0, BH = 16384, BL = 32768;

    extern __shared__ char sm[];
    const uint32_t sb = s2u(sm);

    const int tid  = threadIdx.x;
    const int lane = tid & 31, warp = tid >> 5;
    const int wm = warp >> 1, wn = warp & 1;
    const int nb = blockIdx.x;              // n-block FAST -> A stripe reuse in L2
    const int m0 = blockIdx.y * 128;

    const float* Abase = (MODE == 1) ? Aglob : (const float*)g_x;
    const uint4* Wh = (MODE == 1) ? &g_W1[0][nb][0][0] : &g_W2[0][nb][0][0];
    const uint4* Wl = (MODE == 1) ? &g_W1[1][nb][0][0] : &g_W2[1][nb][0][0];

    float acc[2][8][4] = {};

    const int arow = tid >> 1;
    const int akg  = (tid & 1) * 32;
    const float* aptr = Abase + (size_t)(m0 + arow) * LDA + akg;

    float4 f[8];

    // ---- prologue: stage 0 ----
    {
        const float4* ap = (const float4*)aptr;
        #pragma unroll
        for (int j = 0; j < 8; j++) f[j] = ap[j];
        #pragma unroll
        for (int i = 0; i < 4; i++){
            cpasync16(sb + BH + (tid + 256*i)*16, Wh + tid + 256*i);
            cpasync16(sb + BL + (tid + 256*i)*16, Wl + tid + 256*i);
        }
        asm volatile("cp.async.commit_group;");
        #pragma unroll
        for (int j = 0; j < 4; j++){
            uint4 H;
            H.x = cvt2h(f[2*j].x,   f[2*j].y);
            H.y = cvt2h(f[2*j].z,   f[2*j].w);
            H.z = cvt2h(f[2*j+1].x, f[2*j+1].y);
            H.w = cvt2h(f[2*j+1].z, f[2*j+1].w);
            uint32_t off = SWZ(arow*128 + (tid&1)*64 + j*16);
            *(uint4*)(sm + AH + off) = H;
        }
    }

    for (int kb = 0; kb < KIT; kb++){
        const int cur = kb & 1, nxt = cur ^ 1;
        const uint32_t sc = sb + cur*STG;
        char* smn = sm + nxt*STG;
        const uint32_t sn = sb + nxt*STG;

        if (kb + 1 < KIT){
            const uint4* wh = Wh + (kb+1)*1024;
            const uint4* wl = Wl + (kb+1)*1024;
            #pragma unroll
            for (int i = 0; i < 4; i++){
                cpasync16(sn + BH + (tid + 256*i)*16, wh + tid + 256*i);
                cpasync16(sn + BL + (tid + 256*i)*16, wl + tid + 256*i);
            }
            asm volatile("cp.async.commit_group;");
            const float4* ap = (const float4*)(aptr + (kb+1)*64);
            #pragma unroll
            for (int j = 0; j < 8; j++) f[j] = ap[j];
            asm volatile("cp.async.wait_group 1;" ::: "memory");
        } else {
            asm volatile("cp.async.wait_group 0;" ::: "memory");
        }
        __syncthreads();

        #pragma unroll
        for (int kk = 0; kk < 4; kk++){
            uint4 ah[2];
            #pragma unroll
            for (int mt = 0; mt < 2; mt++){
                uint32_t off = SWZ((wm*32 + mt*16 + (lane&15))*128 + (kk*2 + (lane>>4))*16);
                ah[mt] = ldsm4(sc + AH + off);
            }
            #pragma unroll
            for (int bt = 0; bt < 4; bt++){
                uint32_t off = SWZ((wn*64 + bt*16 + (lane&7) + ((lane>>4)<<3))*128
                                   + (kk*2 + ((lane>>3)&1))*16);
                uint4 bh = ldsm4(sc + BH + off);
                uint4 bl = ldsm4(sc + BL + off);
                #pragma unroll
                for (int mt = 0; mt < 2; mt++){
                    mma16816(acc[mt][2*bt],   ah[mt], bh.x, bh.y);
                    mma16816(acc[mt][2*bt],   ah[mt], bl.x, bl.y);
                    mma16816(acc[mt][2*bt+1], ah[mt], bh.z, bh.w);
                    mma16816(acc[mt][2*bt+1], ah[mt], bl.z, bl.w);
                }
            }
        }

        if (kb + 1 < KIT){
            #pragma unroll
            for (int j = 0; j < 4; j++){
                uint4 H;
                H.x = cvt2h(f[2*j].x,   f[2*j].y);
                H.y = cvt2h(f[2*j].z,   f[2*j].w);
                H.z = cvt2h(f[2*j+1].x, f[2*j+1].y);
                H.w = cvt2h(f[2*j+1].z, f[2*j+1].w);
                uint32_t off = SWZ(arow*128 + (tid&1)*64 + j*16);
                *(uint4*)(smn + AH + off) = H;
            }
        }
        __syncthreads();
    }

    // Epilogue (undo WSCALE)
    const int mrow = lane >> 2;
    const int ncol = (lane & 3) * 2;
    if (MODE == 1){
        #pragma unroll
        for (int mt = 0; mt < 2; mt++){
            #pragma unroll
            for (int nf = 0; nf < 8; nf++){
                int m    = m0 + wm*32 + mt*16 + mrow;
                int neff = nb*128 + wn*64 + nf*8 + ncol;
                int nc   = neff >> 1;
                g_x[(size_t)m*N_ + nc]     = make_float2(acc[mt][nf][0]*WINV, acc[mt][nf][1]*WINV);
                g_x[(size_t)(m+8)*N_ + nc] = make_float2(acc[mt][nf][2]*WINV, acc[mt][nf][3]*WINV);
            }
        }
    } else {
        #pragma unroll
        for (int mt = 0; mt < 2; mt++){
            #pragma unroll
            for (int nf = 0; nf < 8; nf++){
                int m = m0 + wm*32 + mt*16 + mrow;
                int n = nb*128 + wn*64 + nf*8 + ncol;
                float2 d = *(const float2*)&Dv[n];
                size_t i0 = (size_t)m*N_ + n;
                size_t i1 = (size_t)(m+8)*N_ + n;
                float2 u0 = *(const float2*)&uu[i0];
                float2 u1 = *(const float2*)&uu[i1];
                float2 y0 = make_float2(fmaf(d.x, u0.x, acc[mt][nf][0]*WINV),
                                        fmaf(d.y, u0.y, acc[mt][nf][1]*WINV));
                float2 y1 = make_float2(fmaf(d.x, u1.x, acc[mt][nf][2]*WINV),
                                        fmaf(d.y, u1.y, acc[mt][nf][3]*WINV));
                *(float2*)&yout[i0] = y0;
                *(float2*)&yout[i1] = y1;
            }
        }
    }
}

// ---------------------------------------------------------------------------
// Scan pass 1: chunk-local recurrence x_t = lam*x_{t-1} + u_t (in place)
// ---------------------------------------------------------------------------
__global__ __launch_bounds__(256) void scan_local(const float* __restrict__ nu,
                                                  const float* __restrict__ theta)
{
    int gid = blockIdx.x * 256 + threadIdx.x;   // 131072 threads
    int n = gid & (N_-1);
    int c = (gid >> 9) & (NCH_-1);
    int b = gid >> 14;

    float en  = expf(nu[n]);
    float mag = expf(-en);
    float th  = theta[n];
    float lr  = mag * cosf(th);
    float li  = mag * sinf(th);

    float2* p = g_x + ((size_t)(b*T_ + c*L_))*N_ + n;
    float xr = 0.f, xi = 0.f;
    for (int t0 = 0; t0 < L_; t0 += 8){
        float2 v[8];
        #pragma unroll
        for (int j = 0; j < 8; j++) v[j] = p[(size_t)(t0+j)*N_];
        #pragma unroll
        for (int j = 0; j < 8; j++){
            float nr = fmaf(lr, xr, fmaf(-li, xi, v[j].x));
            float ni = fmaf(lr, xi, fmaf( li, xr, v[j].y));
            xr = nr; xi = ni;
            p[(size_t)(t0+j)*N_] = make_float2(xr, xi);
        }
    }
    g_end[(b*NCH_ + c)*N_ + n] = make_float2(xr, xi);
}

// ---------------------------------------------------------------------------
// Scan pass 2: fold carry from previous chunks
// ---------------------------------------------------------------------------
__global__ __launch_bounds__(256) void scan_fix(const float* __restrict__ nu,
                                                const float* __restrict__ theta)
{
    int gid = blockIdx.x * 256 + threadIdx.x;
    int n = gid & (N_-1);
    int c = (gid >> 9) & (NCH_-1);
    int b = gid >> 14;
    if (c == 0) return;

    float en  = expf(nu[n]);
    float mag = expf(-en);
    float th  = theta[n];
    float lr  = mag * cosf(th);
    float li  = mag * sinf(th);

    float magL = expf(-(float)L_ * en);
    float aL   = (float)L_ * th;
    float lLr  = magL * cosf(aL);
    float lLi  = magL * sinf(aL);

    float cr = 0.f, ci = 0.f;
    for (int j = 0; j < c; j++){
        float2 e = g_end[(b*NCH_ + j)*N_ + n];
        float tr = cr*lLr - ci*lLi + e.x;
        float ti = cr*lLi + ci*lLr + e.y;
        cr = tr; ci = ti;
    }

    float2* p = g_x + ((size_t)(b*T_ + c*L_))*N_ + n;
    float pr = lr, pi = li;
    for (int t0 = 0; t0 < L_; t0 += 8){
        float2 v[8];
        #pragma unroll
        for (int j = 0; j < 8; j++) v[j] = p[(size_t)(t0+j)*N_];
        #pragma unroll
        for (int j = 0; j < 8; j++){
            v[j].x += pr*cr - pi*ci;
            v[j].y += pr*ci + pi*cr;
            p[(size_t)(t0+j)*N_] = v[j];
            float npr = pr*lr - pi*li;
            float npi = pr*li + pi*lr;
            pr = npr; pi = npi;
        }
    }
}

// ---------------------------------------------------------------------------
extern "C" void kernel_launch(void* const* d_in, const int* in_sizes, int n_in,
                              void* d_out, int out_size)
{
    const float* u     = (const float*)d_in[0];
    const float* C_re  = (const float*)d_in[1];
    const float* C_im  = (const float*)d_in[2];
    const float* B_re  = (const float*)d_in[3];
    const float* B_im  = (const float*)d_in[4];
    const float* D     = (const float*)d_in[5];
    const float* nu    = (const float*)d_in[6];
    const float* theta = (const float*)d_in[7];
    const float* gamma = (const float*)d_in[8];
    float* y = (float*)d_out;

    const int SMEM = 98304;
    cudaFuncSetAttribute(gemm_tc<1>, cudaFuncAttributeMaxDynamicSharedMemorySize, SMEM);
    cudaFuncSetAttribute(gemm_tc<2>, cudaFuncAttributeMaxDynamicSharedMemorySize, SMEM);

    prep_W<<<512, 256>>>(B_re, B_im, C_re, C_im, gamma);

    gemm_tc<1><<<dim3(8, M_/128), 256, SMEM>>>(u, D, u, (float*)0);

    int scan_threads = B_ * NCH_ * N_;          // 131072
    scan_local<<<scan_threads/256, 256>>>(nu, theta);
    scan_fix<<<scan_threads/256, 256>>>(nu, theta);

    gemm_tc<2><<<dim3(4, M_/128), 256, SMEM>>>((const float*)0, D, u, y);
}

// round 7
// speedup vs baseline: 5.8130x; 1.7372x over previous
#include <cuda_runtime.h>
#include <cuda_fp16.h>
#include <cstdint>

#define B_   8
#define T_   2048
#define N_   512
#define M_   (B_*T_)      // 16384
#define L_   64           // scan chunk length
#define NCH_ (T_/L_)      // 32

#define WSCALE 64.0f
#define WINV   (1.0f/64.0f)

typedef unsigned long long ull;

// Scratch
__device__ __half2 g_xh[M_*N_];               // x as fp16 complex (re=low, im=high)
__device__ float2  g_end[B_*NCH_*N_];
// Pre-transposed/swizzled fp16 weight tiles (scaled by WSCALE):
__device__ uint4 g_W1[8][8][1024];            // GEMM1 B'' (Neff=1024, K=512)
__device__ uint4 g_W2[4][16][1024];           // GEMM2 B'  (N=512, Keff=1024)

// ---------------------------------------------------------------------------
// Helpers
// ---------------------------------------------------------------------------
__device__ __forceinline__ uint32_t s2u(const void* p){
    uint32_t a;
    asm("{ .reg .u64 t; cvta.to.shared.u64 t, %1; cvt.u32.u64 %0, t; }" : "=r"(a) : "l"(p));
    return a;
}
#define SWZ(o) ((uint32_t)(o) ^ ((((uint32_t)(o))>>3)&0x70u))

__device__ __forceinline__ uint32_t cvt2h(float x0, float x1){
    uint32_t r;
    asm("cvt.rn.f16x2.f32 %0, %1, %2;" : "=r"(r) : "f"(x1), "f"(x0));
    return r;
}
__device__ __forceinline__ uint4 ldsm4(uint32_t addr){
    uint4 r;
    asm volatile("ldmatrix.sync.aligned.m8n8.x4.shared.b16 {%0,%1,%2,%3}, [%4];"
        : "=r"(r.x), "=r"(r.y), "=r"(r.z), "=r"(r.w) : "r"(addr));
    return r;
}
__device__ __forceinline__ void mma16816(float* c, uint4 a, uint32_t b0, uint32_t b1){
    asm volatile("mma.sync.aligned.m16n8k16.row.col.f32.f16.f16.f32 "
        "{%0,%1,%2,%3}, {%4,%5,%6,%7}, {%8,%9}, {%0,%1,%2,%3};"
        : "+f"(c[0]), "+f"(c[1]), "+f"(c[2]), "+f"(c[3])
        : "r"(a.x), "r"(a.y), "r"(a.z), "r"(a.w), "r"(b0), "r"(b1));
}
__device__ __forceinline__ void cpasync16(uint32_t dst, const void* src){
    asm volatile("cp.async.cg.shared.global [%0], [%1], 16;" :: "r"(dst), "l"(src));
}

// ---------------------------------------------------------------------------
// Prepass: transpose + fp16 (x WSCALE) + swizzle weights (single plane).
// ---------------------------------------------------------------------------
__global__ __launch_bounds__(256) void prep_W(const float* __restrict__ Bre,
                                              const float* __restrict__ Bim,
                                              const float* __restrict__ Cre,
                                              const float* __restrict__ Cim,
                                              const float* __restrict__ gamma)
{
    int v = blockIdx.x * 256 + threadIdx.x;        // 0 .. 131071
    if (v < 65536){
        int j = v >> 6, c = v & 63;
        int nb = j >> 7, jl = j & 127, kb = c >> 3, cl = c & 7;
        const float* src = (j & 1) ? Bim : Bre;
        int n = j >> 1;
        float vs[8];
        #pragma unroll
        for (int kk = 0; kk < 8; kk++){
            int k = c*8 + kk;
            vs[kk] = src[(size_t)k*N_ + n] * gamma[k] * WSCALE;
        }
        uint4 H;
        H.x = cvt2h(vs[0], vs[1]);
        H.y = cvt2h(vs[2], vs[3]);
        H.z = cvt2h(vs[4], vs[5]);
        H.w = cvt2h(vs[6], vs[7]);
        g_W1[nb][kb][jl*8 + (cl ^ (jl & 7))] = H;
    } else {
        v -= 65536;
        int j = v >> 7, c = v & 127;
        int nb = j >> 7, jl = j & 127, kb = c >> 3, cl = c & 7;
        float vs[8];
        #pragma unroll
        for (int e = 0; e < 8; e++){
            int keff = c*8 + e;
            int k = keff >> 1;
            vs[e] = ((keff & 1) ? -Cim[(size_t)k*N_ + j] : Cre[(size_t)k*N_ + j]) * WSCALE;
        }
        uint4 H;
        H.x = cvt2h(vs[0], vs[1]);
        H.y = cvt2h(vs[2], vs[3]);
        H.z = cvt2h(vs[4], vs[5]);
        H.w = cvt2h(vs[6], vs[7]);
        g_W2[nb][kb][jl*8 + (cl ^ (jl & 7))] = H;
    }
}

// ---------------------------------------------------------------------------
// HMMA GEMM, single fp16 product, double-buffered.
// MODE 1: g_xh = u @ W1 (fp32 A, cvt in-kernel),  M=16384, Neff=1024, K=512
// MODE 2: y = flat16(g_xh) @ W2 + D*u (A pure cp.async), M=16384, N=512, Keff=1024
// CTA tile 128x128x64, 8 warps (4x2), warp tile 32x64.
// ---------------------------------------------------------------------------
template<int MODE>
__global__ __launch_bounds__(256, 2) void gemm_tc(const float* __restrict__ Aglob,
                                                  const float* __restrict__ Dv,
                                                  const float* __restrict__ uu,
                                                  float* __restrict__ yout)
{
    constexpr int KIT = (MODE == 1) ? 8 : 16;
    constexpr uint32_t STG = 32768;
    constexpr uint32_t AH = 0, BH = 16384;

    extern __shared__ char sm[];
    const uint32_t sb = s2u(sm);

    const int tid  = threadIdx.x;
    const int lane = tid & 31, warp = tid >> 5;
    const int wm = warp >> 1, wn = warp & 1;
    const int nb = blockIdx.x;              // n-block FAST -> A stripe reuse in L2
    const int m0 = blockIdx.y * 128;

    const uint4* Wh = (MODE == 1) ? &g_W1[nb][0][0] : &g_W2[nb][0][0];

    float acc[2][8][4] = {};

    // MODE1 A-load mapping
    const int arow = tid >> 1;
    const int akg  = (tid & 1) * 32;
    const float* aptr = (MODE == 1) ? (Aglob + (size_t)(m0 + arow) * 512 + akg) : (const float*)0;
    float4 f[8];

    // MODE2 A cp.async mapping: 1024 16B units (row 0..127, u 0..7), 4 per thread
    // unit idx = tid + 256*i : row = idx>>3, u = idx&7

    // ---- prologue: stage 0 ----
    {
        #pragma unroll
        for (int i = 0; i < 4; i++)
            cpasync16(sb + BH + (tid + 256*i)*16, Wh + tid + 256*i);
        if (MODE == 2){
            #pragma unroll
            for (int i = 0; i < 4; i++){
                int idx = tid + 256*i, row = idx >> 3, un = idx & 7;
                cpasync16(sb + AH + SWZ(row*128 + un*16),
                          (const uint4*)(g_xh + (size_t)(m0+row)*512) + un);
            }
        }
        asm volatile("cp.async.commit_group;");
        if (MODE == 1){
            const float4* ap = (const float4*)aptr;
            #pragma unroll
            for (int j = 0; j < 8; j++) f[j] = ap[j];
            #pragma unroll
            for (int j = 0; j < 4; j++){
                uint4 H;
                H.x = cvt2h(f[2*j].x,   f[2*j].y);
                H.y = cvt2h(f[2*j].z,   f[2*j].w);
                H.z = cvt2h(f[2*j+1].x, f[2*j+1].y);
                H.w = cvt2h(f[2*j+1].z, f[2*j+1].w);
                *(uint4*)(sm + AH + SWZ(arow*128 + (tid&1)*64 + j*16)) = H;
            }
        }
    }

    for (int kb = 0; kb < KIT; kb++){
        const int cur = kb & 1, nxt = cur ^ 1;
        const uint32_t sc = sb + cur*STG;
        char* smn = sm + nxt*STG;
        const uint32_t sn = sb + nxt*STG;

        if (kb + 1 < KIT){
            const uint4* wh = Wh + (kb+1)*1024;
            #pragma unroll
            for (int i = 0; i < 4; i++)
                cpasync16(sn + BH + (tid + 256*i)*16, wh + tid + 256*i);
            if (MODE == 2){
                #pragma unroll
                for (int i = 0; i < 4; i++){
                    int idx = tid + 256*i, row = idx >> 3, un = idx & 7;
                    cpasync16(sn + AH + SWZ(row*128 + un*16),
                              (const uint4*)(g_xh + (size_t)(m0+row)*512 + (kb+1)*32) + un);
                }
            }
            asm volatile("cp.async.commit_group;");
            if (MODE == 1){
                const float4* ap = (const float4*)(aptr + (kb+1)*64);
                #pragma unroll
                for (int j = 0; j < 8; j++) f[j] = ap[j];
            }
            asm volatile("cp.async.wait_group 1;" ::: "memory");
        } else {
            asm volatile("cp.async.wait_group 0;" ::: "memory");
        }
        __syncthreads();

        #pragma unroll
        for (int kk = 0; kk < 4; kk++){
            uint4 ah[2];
            #pragma unroll
            for (int mt = 0; mt < 2; mt++){
                uint32_t off = SWZ((wm*32 + mt*16 + (lane&15))*128 + (kk*2 + (lane>>4))*16);
                ah[mt] = ldsm4(sc + AH + off);
            }
            #pragma unroll
            for (int bt = 0; bt < 4; bt++){
                uint32_t off = SWZ((wn*64 + bt*16 + (lane&7) + ((lane>>4)<<3))*128
                                   + (kk*2 + ((lane>>3)&1))*16);
                uint4 bh = ldsm4(sc + BH + off);
                #pragma unroll
                for (int mt = 0; mt < 2; mt++){
                    mma16816(acc[mt][2*bt],   ah[mt], bh.x, bh.y);
                    mma16816(acc[mt][2*bt+1], ah[mt], bh.z, bh.w);
                }
            }
        }

        if (MODE == 1 && kb + 1 < KIT){
            #pragma unroll
            for (int j = 0; j < 4; j++){
                uint4 H;
                H.x = cvt2h(f[2*j].x,   f[2*j].y);
                H.y = cvt2h(f[2*j].z,   f[2*j].w);
                H.z = cvt2h(f[2*j+1].x, f[2*j+1].y);
                H.w = cvt2h(f[2*j+1].z, f[2*j+1].w);
                *(uint4*)(smn + AH + SWZ(arow*128 + (tid&1)*64 + j*16)) = H;
            }
        }
        __syncthreads();
    }

    // Epilogue (undo WSCALE)
    const int mrow = lane >> 2;
    const int ncol = (lane & 3) * 2;
    if (MODE == 1){
        #pragma unroll
        for (int mt = 0; mt < 2; mt++){
            #pragma unroll
            for (int nf = 0; nf < 8; nf++){
                int m    = m0 + wm*32 + mt*16 + mrow;
                int neff = nb*128 + wn*64 + nf*8 + ncol;
                int nc   = neff >> 1;
                g_xh[(size_t)m*N_ + nc]     = __floats2half2_rn(acc[mt][nf][0]*WINV, acc[mt][nf][1]*WINV);
                g_xh[(size_t)(m+8)*N_ + nc] = __floats2half2_rn(acc[mt][nf][2]*WINV, acc[mt][nf][3]*WINV);
            }
        }
    } else {
        #pragma unroll
        for (int mt = 0; mt < 2; mt++){
            #pragma unroll
            for (int nf = 0; nf < 8; nf++){
                int m = m0 + wm*32 + mt*16 + mrow;
                int n = nb*128 + wn*64 + nf*8 + ncol;
                float2 d = *(const float2*)&Dv[n];
                size_t i0 = (size_t)m*N_ + n;
                size_t i1 = (size_t)(m+8)*N_ + n;
                float2 u0 = *(const float2*)&uu[i0];
                float2 u1 = *(const float2*)&uu[i1];
                float2 y0 = make_float2(fmaf(d.x, u0.x, acc[mt][nf][0]*WINV),
                                        fmaf(d.y, u0.y, acc[mt][nf][1]*WINV));
                float2 y1 = make_float2(fmaf(d.x, u1.x, acc[mt][nf][2]*WINV),
                                        fmaf(d.y, u1.y, acc[mt][nf][3]*WINV));
                *(float2*)&yout[i0] = y0;
                *(float2*)&yout[i1] = y1;
            }
        }
    }
}

// ---------------------------------------------------------------------------
// Scan pass 1: chunk-local recurrence x_t = lam*x_{t-1} + u_t (in place, fp16)
// ---------------------------------------------------------------------------
__global__ __launch_bounds__(256) void scan_local(const float* __restrict__ nu,
                                                  const float* __restrict__ theta)
{
    int gid = blockIdx.x * 256 + threadIdx.x;   // 131072 threads
    int n = gid & (N_-1);
    int c = (gid >> 9) & (NCH_-1);
    int b = gid >> 14;

    float en  = expf(nu[n]);
    float mag = expf(-en);
    float th  = theta[n];
    float lr  = mag * cosf(th);
    float li  = mag * sinf(th);

    __half2* p = g_xh + ((size_t)(b*T_ + c*L_))*N_ + n;
    float xr = 0.f, xi = 0.f;
    for (int t0 = 0; t0 < L_; t0 += 16){
        __half2 v[16];
        #pragma unroll
        for (int j = 0; j < 16; j++) v[j] = p[(size_t)(t0+j)*N_];
        #pragma unroll
        for (int j = 0; j < 16; j++){
            float2 q = __half22float2(v[j]);
            float nr = fmaf(lr, xr, fmaf(-li, xi, q.x));
            float ni = fmaf(lr, xi, fmaf( li, xr, q.y));
            xr = nr; xi = ni;
            p[(size_t)(t0+j)*N_] = __floats2half2_rn(xr, xi);
        }
    }
    g_end[(b*NCH_ + c)*N_ + n] = make_float2(xr, xi);
}

// ---------------------------------------------------------------------------
// Scan pass 2: fold carry from previous chunks (fp16 RMW)
// ---------------------------------------------------------------------------
__global__ __launch_bounds__(256) void scan_fix(const float* __restrict__ nu,
                                                const float* __restrict__ theta)
{
    int gid = blockIdx.x * 256 + threadIdx.x;
    int n = gid & (N_-1);
    int c = (gid >> 9) & (NCH_-1);
    int b = gid >> 14;
    if (c == 0) return;

    float en  = expf(nu[n]);
    float mag = expf(-en);
    float th  = theta[n];
    float lr  = mag * cosf(th);
    float li  = mag * sinf(th);

    float magL = expf(-(float)L_ * en);
    float aL   = (float)L_ * th;
    float lLr  = magL * cosf(aL);
    float lLi  = magL * sinf(aL);

    float cr = 0.f, ci = 0.f;
    for (int j = 0; j < c; j++){
        float2 e = g_end[(b*NCH_ + j)*N_ + n];
        float tr = cr*lLr - ci*lLi + e.x;
        float ti = cr*lLi + ci*lLr + e.y;
        cr = tr; ci = ti;
    }

    __half2* p = g_xh + ((size_t)(b*T_ + c*L_))*N_ + n;
    float pr = lr, pi = li;
    for (int t0 = 0; t0 < L_; t0 += 16){
        __half2 v[16];
        #pragma unroll
        for (int j = 0; j < 16; j++) v[j] = p[(size_t)(t0+j)*N_];
        #pragma unroll
        for (int j = 0; j < 16; j++){
            float2 q = __half22float2(v[j]);
            q.x += pr*cr - pi*ci;
            q.y += pr*ci + pi*cr;
            p[(size_t)(t0+j)*N_] = __floats2half2_rn(q.x, q.y);
            float npr = pr*lr - pi*li;
            float npi = pr*li + pi*lr;
            pr = npr; pi = npi;
        }
    }
}

// ---------------------------------------------------------------------------
extern "C" void kernel_launch(void* const* d_in, const int* in_sizes, int n_in,
                              void* d_out, int out_size)
{
    const float* u     = (const float*)d_in[0];
    const float* C_re  = (const float*)d_in[1];
    const float* C_im  = (const float*)d_in[2];
    const float* B_re  = (const float*)d_in[3];
    const float* B_im  = (const float*)d_in[4];
    const float* D     = (const float*)d_in[5];
    const float* nu    = (const float*)d_in[6];
    const float* theta = (const float*)d_in[7];
    const float* gamma = (const float*)d_in[8];
    float* y = (float*)d_out;

    const int SMEM = 65536;
    cudaFuncSetAttribute(gemm_tc<1>, cudaFuncAttributeMaxDynamicSharedMemorySize, SMEM);
    cudaFuncSetAttribute(gemm_tc<2>, cudaFuncAttributeMaxDynamicSharedMemorySize, SMEM);

    prep_W<<<512, 256>>>(B_re, B_im, C_re, C_im, gamma);

    gemm_tc<1><<<dim3(8, M_/128), 256, SMEM>>>(u, D, u, (float*)0);

    scan_local<<<512, 256>>>(nu, theta);
    scan_fix<<<512, 256>>>(nu, theta);

    gemm_tc<2><<<dim3(4, M_/128), 256, SMEM>>>((const float*)0, D, u, y);
}